// round 9
// baseline (speedup 1.0000x reference)
#include <cuda_runtime.h>
#include <cuda_fp16.h>

// RoiAlign: feature_map (4, 256, 50, 50) f32, boxes (512,4) f32, box_idx (512) i32
// Output: (512, 256, 14, 14) f32
//
// R8 was issue-volume bound; the compute phase spent most slots on half->float
// unpacks (32 F2F + 32 FFMA per 8 outputs). R9 does the bilinear weighted sum
// directly in half2 (HMUL2/HFMA2), converting only the final result to f32.
// ~2x fewer compute-phase instructions. Weights (incl. validity) in half2.

#define CROP    14
#define NPIX    (CROP * CROP)      // 196
#define FM_H    50
#define FM_W    50
#define FM_HW   (FM_H * FM_W)      // 2500
#define NCHAN   256
#define NBOX    512
#define CPB     32                 // channels per block
#define NCG8    (CPB / 8)          // 4 groups of 8 channels
#define WIN     16
#define NCELL   (WIN * WIN)        // 256 cells (fixed layout)
#define THREADS 224                // 7 full warps

struct alignas(16) h2x4 {          // 8 fp16 values = one 16-byte smem cell
    __half2 a, b, c, d;
};

__global__ __launch_bounds__(THREADS) void roi_align_kernel(
    const float* __restrict__ fm,
    const float* __restrict__ boxes,
    const int*   __restrict__ box_idx,
    float*       __restrict__ out)
{
    __shared__ h2x4 s4[NCG8 * NCELL];   // 16 KB

    const int m   = blockIdx.x;               // box
    const int cb  = blockIdx.y * CPB;         // channel base
    const int tid = threadIdx.x;

    // ---- Per-box geometry ----
    const float inv_stride = 1.0f / 16.0f;
    const float inv_span   = 1.0f / (float)(CROP - 1);
    const float bx1 = boxes[m * 4 + 0] * inv_stride;
    const float by1 = boxes[m * 4 + 1] * inv_stride;
    const float bx2 = boxes[m * 4 + 2] * inv_stride;
    const float by2 = boxes[m * 4 + 3] * inv_stride;

    const int ystart = min(max((int)floorf(by1), 0), FM_H - 1);
    const int xstart = min(max((int)floorf(bx1), 0), FM_W - 1);

    // Trimmed staging extents (+margin for fp rounding at far edge).
    const int yendc = min(max((int)floorf(by2), 0), FM_H - 1);
    const int xendc = min(max((int)floorf(bx2), 0), FM_W - 1);
    const int wyn = min(yendc - ystart + 3, WIN);
    const int wxn = min(xendc - xstart + 3, WIN);

    const int bi = box_idx[m];
    const float* __restrict__ fbase =
        fm + (size_t)bi * NCHAN * FM_HW + (size_t)cb * FM_HW;

    // ---- Stage: wyn x wxn cells per channel group, fixed 16-stride layout ----
    const int cells = wyn << 4;
    #pragma unroll
    for (int cg = 0; cg < NCG8; ++cg) {
        const float* __restrict__ fc = fbase + cg * 8 * FM_HW;
        for (int r = tid; r < cells; r += THREADS) {
            const int ry = r >> 4;
            const int rx = r & 15;
            if (rx < wxn) {
                const int gy = min(ystart + ry, FM_H - 1);
                const int gx = min(xstart + rx, FM_W - 1);
                const float* p = fc + gy * FM_W + gx;
                h2x4 packed;
                packed.a = __float22half2_rn(make_float2(__ldg(p),             __ldg(p + FM_HW)));
                packed.b = __float22half2_rn(make_float2(__ldg(p + 2 * FM_HW), __ldg(p + 3 * FM_HW)));
                packed.c = __float22half2_rn(make_float2(__ldg(p + 4 * FM_HW), __ldg(p + 5 * FM_HW)));
                packed.d = __float22half2_rn(make_float2(__ldg(p + 6 * FM_HW), __ldg(p + 7 * FM_HW)));
                s4[cg * NCELL + r] = packed;
            }
        }
    }
    __syncthreads();

    if (tid >= NPIX) return;

    // ---- Per-pixel sampling point ----
    const int iy = tid / CROP;
    const int ix = tid - iy * CROP;

    const float ys = by1 + (float)iy * (by2 - by1) * inv_span;
    const float xs = bx1 + (float)ix * (bx2 - bx1) * inv_span;

    const float y0f = floorf(ys);
    const float x0f = floorf(xs);
    const int y0 = min(max((int)y0f, 0), FM_H - 1);
    const int x0 = min(max((int)x0f, 0), FM_W - 1);
    const int y1 = min(y0 + 1, FM_H - 1);
    const int x1 = min(x0 + 1, FM_W - 1);
    const float wy = ys - y0f;
    const float wx = xs - x0f;
    const float v  = (ys >= 0.0f && ys <= (float)(FM_H - 1) &&
                      xs >= 0.0f && xs <= (float)(FM_W - 1)) ? 1.0f : 0.0f;

    const int l00 = (y0 - ystart) * WIN + (x0 - xstart);
    const int dx  = x1 - x0;            // 0 or 1
    const int dyc = (y1 - y0) * WIN;    // 0 or 16

    // Folded weights (incl. validity), broadcast to half2.
    const __half2 hw00 = __float2half2_rn((1.0f - wx) * (1.0f - wy) * v);
    const __half2 hw01 = __float2half2_rn(wx * (1.0f - wy) * v);
    const __half2 hw10 = __float2half2_rn((1.0f - wx) * wy * v);
    const __half2 hw11 = __float2half2_rn(wx * wy * v);

    float* __restrict__ o =
        out + (size_t)m * NCHAN * NPIX + (size_t)cb * NPIX + tid;

    #pragma unroll
    for (int cg = 0; cg < NCG8; ++cg) {
        const h2x4* sc = s4 + cg * NCELL;
        const h2x4 pa = sc[l00];
        const h2x4 pb = sc[l00 + dx];
        const h2x4 pc = sc[l00 + dyc];
        const h2x4 pd = sc[l00 + dyc + dx];

        float* oc = o + cg * 8 * NPIX;

        #pragma unroll
        for (int j = 0; j < 4; ++j) {
            __half2 r = __hmul2((&pa.a)[j], hw00);
            r = __hfma2((&pb.a)[j], hw01, r);
            r = __hfma2((&pc.a)[j], hw10, r);
            r = __hfma2((&pd.a)[j], hw11, r);
            const float2 rf = __half22float2(r);
            oc[(2 * j)     * NPIX] = rf.x;
            oc[(2 * j + 1) * NPIX] = rf.y;
        }
    }
}

extern "C" void kernel_launch(void* const* d_in, const int* in_sizes, int n_in,
                              void* d_out, int out_size)
{
    const float* fm     = (const float*)d_in[0];
    const float* boxes  = (const float*)d_in[1];
    const int*   boxidx = (const int*)d_in[2];
    float*       out    = (float*)d_out;

    dim3 grid(NBOX, NCHAN / CPB);   // (512, 8) = 4096 blocks
    roi_align_kernel<<<grid, THREADS>>>(fm, boxes, boxidx, out);
}

// round 10
// speedup vs baseline: 1.1302x; 1.1302x over previous
#include <cuda_runtime.h>
#include <cuda_fp16.h>

// RoiAlign: feature_map (4, 256, 50, 50) f32, boxes (512,4) f32, box_idx (512) i32
// Output: (512, 256, 14, 14) f32
//
// R9 cut compute instructions ~35% via half2 math but regs 32->40 dropped
// occupancy to 58% and the serial hfma2 chain exposed latency -> regression.
// R10 = R9 + __launch_bounds__(224, 9) (forces 32 regs, restores ~63-warp
// residency) + tree-form reduction (depth 4 -> 3, two independent chains).

#define CROP    14
#define NPIX    (CROP * CROP)      // 196
#define FM_H    50
#define FM_W    50
#define FM_HW   (FM_H * FM_W)      // 2500
#define NCHAN   256
#define NBOX    512
#define CPB     32                 // channels per block
#define NCG8    (CPB / 8)          // 4 groups of 8 channels
#define WIN     16
#define NCELL   (WIN * WIN)        // 256 cells (fixed layout)
#define THREADS 224                // 7 full warps

struct alignas(16) h2x4 {          // 8 fp16 values = one 16-byte smem cell
    __half2 a, b, c, d;
};

__global__ __launch_bounds__(THREADS, 9) void roi_align_kernel(
    const float* __restrict__ fm,
    const float* __restrict__ boxes,
    const int*   __restrict__ box_idx,
    float*       __restrict__ out)
{
    __shared__ h2x4 s4[NCG8 * NCELL];   // 16 KB

    const int m   = blockIdx.x;               // box
    const int cb  = blockIdx.y * CPB;         // channel base
    const int tid = threadIdx.x;

    // ---- Per-box geometry ----
    const float inv_stride = 1.0f / 16.0f;
    const float inv_span   = 1.0f / (float)(CROP - 1);
    const float bx1 = boxes[m * 4 + 0] * inv_stride;
    const float by1 = boxes[m * 4 + 1] * inv_stride;
    const float bx2 = boxes[m * 4 + 2] * inv_stride;
    const float by2 = boxes[m * 4 + 3] * inv_stride;

    const int ystart = min(max((int)floorf(by1), 0), FM_H - 1);
    const int xstart = min(max((int)floorf(bx1), 0), FM_W - 1);

    // Trimmed staging extents (+margin for fp rounding at far edge).
    const int yendc = min(max((int)floorf(by2), 0), FM_H - 1);
    const int xendc = min(max((int)floorf(bx2), 0), FM_W - 1);
    const int wyn = min(yendc - ystart + 3, WIN);
    const int wxn = min(xendc - xstart + 3, WIN);

    const int bi = box_idx[m];
    const float* __restrict__ fbase =
        fm + (size_t)bi * NCHAN * FM_HW + (size_t)cb * FM_HW;

    // ---- Stage: wyn x wxn cells per channel group, fixed 16-stride layout ----
    const int cells = wyn << 4;
    #pragma unroll
    for (int cg = 0; cg < NCG8; ++cg) {
        const float* __restrict__ fc = fbase + cg * 8 * FM_HW;
        for (int r = tid; r < cells; r += THREADS) {
            const int ry = r >> 4;
            const int rx = r & 15;
            if (rx < wxn) {
                const int gy = min(ystart + ry, FM_H - 1);
                const int gx = min(xstart + rx, FM_W - 1);
                const float* p = fc + gy * FM_W + gx;
                h2x4 packed;
                packed.a = __float22half2_rn(make_float2(__ldg(p),             __ldg(p + FM_HW)));
                packed.b = __float22half2_rn(make_float2(__ldg(p + 2 * FM_HW), __ldg(p + 3 * FM_HW)));
                packed.c = __float22half2_rn(make_float2(__ldg(p + 4 * FM_HW), __ldg(p + 5 * FM_HW)));
                packed.d = __float22half2_rn(make_float2(__ldg(p + 6 * FM_HW), __ldg(p + 7 * FM_HW)));
                s4[cg * NCELL + r] = packed;
            }
        }
    }
    __syncthreads();

    if (tid >= NPIX) return;

    // ---- Per-pixel sampling point ----
    const int iy = tid / CROP;
    const int ix = tid - iy * CROP;

    const float ys = by1 + (float)iy * (by2 - by1) * inv_span;
    const float xs = bx1 + (float)ix * (bx2 - bx1) * inv_span;

    const float y0f = floorf(ys);
    const float x0f = floorf(xs);
    const int y0 = min(max((int)y0f, 0), FM_H - 1);
    const int x0 = min(max((int)x0f, 0), FM_W - 1);
    const int y1 = min(y0 + 1, FM_H - 1);
    const int x1 = min(x0 + 1, FM_W - 1);
    const float wy = ys - y0f;
    const float wx = xs - x0f;
    const float v  = (ys >= 0.0f && ys <= (float)(FM_H - 1) &&
                      xs >= 0.0f && xs <= (float)(FM_W - 1)) ? 1.0f : 0.0f;

    const int l00 = (y0 - ystart) * WIN + (x0 - xstart);
    const int dx  = x1 - x0;            // 0 or 1
    const int dyc = (y1 - y0) * WIN;    // 0 or 16

    // Folded weights (incl. validity), broadcast to half2.
    const __half2 hw00 = __float2half2_rn((1.0f - wx) * (1.0f - wy) * v);
    const __half2 hw01 = __float2half2_rn(wx * (1.0f - wy) * v);
    const __half2 hw10 = __float2half2_rn((1.0f - wx) * wy * v);
    const __half2 hw11 = __float2half2_rn(wx * wy * v);

    float* __restrict__ o =
        out + (size_t)m * NCHAN * NPIX + (size_t)cb * NPIX + tid;

    #pragma unroll
    for (int cg = 0; cg < NCG8; ++cg) {
        const h2x4* sc = s4 + cg * NCELL;
        const h2x4 pa = sc[l00];
        const h2x4 pb = sc[l00 + dx];
        const h2x4 pc = sc[l00 + dyc];
        const h2x4 pd = sc[l00 + dyc + dx];

        float* oc = o + cg * 8 * NPIX;

        #pragma unroll
        for (int j = 0; j < 4; ++j) {
            // Tree form: two independent chains, depth 3.
            __half2 u = __hfma2((&pb.a)[j], hw01, __hmul2((&pa.a)[j], hw00));
            __half2 w = __hfma2((&pd.a)[j], hw11, __hmul2((&pc.a)[j], hw10));
            __half2 r = __hadd2(u, w);
            const float2 rf = __half22float2(r);
            oc[(2 * j)     * NPIX] = rf.x;
            oc[(2 * j + 1) * NPIX] = rf.y;
        }
    }
}

extern "C" void kernel_launch(void* const* d_in, const int* in_sizes, int n_in,
                              void* d_out, int out_size)
{
    const float* fm     = (const float*)d_in[0];
    const float* boxes  = (const float*)d_in[1];
    const int*   boxidx = (const int*)d_in[2];
    float*       out    = (float*)d_out;

    dim3 grid(NBOX, NCHAN / CPB);   // (512, 8) = 4096 blocks
    roi_align_kernel<<<grid, THREADS>>>(fm, boxes, boxidx, out);
}